// round 1
// baseline (speedup 1.0000x reference)
#include <cuda_runtime.h>

#define Fq   20
#define Dq   16
#define Hq   2
#define NBq  500000
#define Bq   4096
#define NIq  190          // F*(F-1)/2
#define FDq  320          // F*D

// Scratch (device globals: no allocation allowed in kernel_launch)
__device__ float g_W12[FDq * NIq];   // w1 @ w2  (320 x 190)
__device__ float g_W[Bq * NIq];      // z @ W12  (4096 x 190)

// ---------------------------------------------------------------------------
// Kernel A: W12 = senet_w1 @ senet_w2   (320x320 @ 320x190) — 19.5M MACs
// ---------------------------------------------------------------------------
__global__ void k_w12(const float* __restrict__ w1, const float* __restrict__ w2) {
    int idx = blockIdx.x * blockDim.x + threadIdx.x;
    if (idx >= FDq * NIq) return;
    int i = idx / NIq;
    int j = idx - i * NIq;
    float acc = 0.f;
    #pragma unroll 8
    for (int k = 0; k < FDq; k++)
        acc += w1[i * FDq + k] * w2[k * NIq + j];
    g_W12[idx] = acc;
}

// ---------------------------------------------------------------------------
// Kernel B: g_W = Z @ W12   (4096x320 @ 320x190) — 249M MACs
// One block = 16 batch rows, thread j computes column j for all 16 rows.
// ---------------------------------------------------------------------------
#define TBq 16
__global__ void k_senet(const float* __restrict__ z) {
    __shared__ float zs[TBq * FDq];              // 20 KB
    int b0 = blockIdx.x * TBq;
    for (int i = threadIdx.x; i < TBq * FDq; i += blockDim.x)
        zs[i] = z[b0 * FDq + i];
    __syncthreads();
    int j = threadIdx.x;
    if (j >= NIq) return;
    float acc[TBq];
    #pragma unroll
    for (int b = 0; b < TBq; b++) acc[b] = 0.f;
    for (int k = 0; k < FDq; k++) {
        float wv = g_W12[k * NIq + j];           // coalesced across threads
        #pragma unroll
        for (int b = 0; b < TBq; b++)            // zs read is LDS-broadcast
            acc[b] += zs[b * FDq + k] * wv;
    }
    #pragma unroll
    for (int b = 0; b < TBq; b++)
        g_W[(b0 + b) * NIq + j] = acc[b];
}

// ---------------------------------------------------------------------------
// Kernel C: main. One CTA per batch b.
// Phase 1: half-warp per pair j — gather 2 codebook rows, transform by W
//          (column-in-registers, row broadcast via shfl width=16), scale by
//          w[b,j], store to smem (stride 17 to dodge bank conflicts).
// Phase 2: thread per (f,d) output sums its 19 pair contributions. No atomics.
// ---------------------------------------------------------------------------
__global__ __launch_bounds__(256) void k_main(
    const float* __restrict__ codebook,
    const float* __restrict__ Wt,          // (32, 16)
    const int*   __restrict__ hash_idx,    // (2, B, NI)
    const int*   __restrict__ inter,       // (F, F-1)
    float*       __restrict__ out)         // (B, F, D)
{
    __shared__ float embw[NIq * 17];       // weighted emb, padded stride
    __shared__ float ws[NIq];
    __shared__ int   idxs[Fq * (Fq - 1)];  // 380

    const int b   = blockIdx.x;
    const int tid = threadIdx.x;
    const int d   = tid & 15;

    if (tid < NIq) ws[tid] = g_W[b * NIq + tid];
    for (int i = tid; i < Fq * (Fq - 1); i += blockDim.x) idxs[i] = inter[i];

    // W column d into registers (32 regs)
    float wr[2 * Dq];
    #pragma unroll
    for (int k = 0; k < 2 * Dq; k++) wr[k] = Wt[k * Dq + d];
    __syncthreads();

    const int* h0 = hash_idx + b * NIq;
    const int* h1 = hash_idx + Bq * NIq + b * NIq;
    const int half = tid >> 4;             // half-warp id 0..15

    // Trip counts are equal for both halves of every warp (190 = 11*16 + 14),
    // so full-mask width-16 shuffles stay converged.
    for (int j = half; j < NIq; j += 16) {
        int i0 = h0[j];
        int i1 = h1[j];
        float g0 = codebook[i0 * Dq + d];  // 64B coalesced per half-warp
        float g1 = codebook[i1 * Dq + d];
        float acc = 0.f;
        #pragma unroll
        for (int k = 0; k < Dq; k++) {
            acc += __shfl_sync(0xffffffffu, g0, k, 16) * wr[k];
            acc += __shfl_sync(0xffffffffu, g1, k, 16) * wr[Dq + k];
        }
        embw[j * 17 + d] = acc * ws[j];
    }
    __syncthreads();

    // Phase 2: out[b, f, d] = sum over the 19 pairs containing field f
    for (int o = tid; o < Fq * Dq; o += blockDim.x) {
        int f  = o >> 4;
        int dd = o & 15;
        float s = 0.f;
        #pragma unroll
        for (int p = 0; p < Fq - 1; p++) {
            int j = idxs[f * (Fq - 1) + p];
            s += embw[j * 17 + dd];
        }
        out[b * Fq * Dq + o] = s;
    }
}

// ---------------------------------------------------------------------------
extern "C" void kernel_launch(void* const* d_in, const int* in_sizes, int n_in,
                              void* d_out, int out_size) {
    const float* origin   = (const float*)d_in[0];  // (B, F, D)
    const float* codebook = (const float*)d_in[1];  // (NB, D)
    const float* Wt       = (const float*)d_in[2];  // (H*D, D)
    const float* w1       = (const float*)d_in[3];  // (FD, FD)
    const float* w2       = (const float*)d_in[4];  // (FD, NI)
    const int*   hash     = (const int*)d_in[5];    // (H, B, NI)
    const int*   inter    = (const int*)d_in[6];    // (F, F-1)
    float*       out      = (float*)d_out;

    k_w12<<<(FDq * NIq + 255) / 256, 256>>>(w1, w2);
    k_senet<<<Bq / TBq, 192>>>(origin);
    k_main<<<Bq, 256>>>(codebook, Wt, hash, inter, out);
}

// round 3
// speedup vs baseline: 1.2928x; 1.2928x over previous
#include <cuda_runtime.h>

#define Fq   20
#define Dq   16
#define NBq  500000
#define Bq   4096
#define NIq  190          // F*(F-1)/2
#define FDq  320          // F*D

// Device-global scratch (no runtime allocation allowed).
// __align__(16): these are accessed through float4.
__device__ __align__(16) float g_W12T[NIq * FDq];   // (w1@w2)^T : [j][k]
__device__ __align__(16) float g_W[Bq * NIq];       // z@w1@w2 : [b][j]
__device__ __align__(16) float g_CT0[NBq * Dq];     // codebook @ W_top : 32 MB
__device__ __align__(16) float g_CT1[NBq * Dq];     // codebook @ W_bot : 32 MB

#define W12_TILES 60                      // 10 M-tiles x 6 N-tiles (32x32)
#define CT_BLOCKS ((NBq + 255) / 256)     // 1954

// ---------------------------------------------------------------------------
// K1 (fused, grid-split):
//   blocks [0,60): tiled GEMM  W12T = (w1 @ w2)^T        (320x320x190)
//   blocks [60,..): codebook transform CT0/CT1            (500000 rows)
// ---------------------------------------------------------------------------
__global__ __launch_bounds__(256) void k_pre(
    const float* __restrict__ w1,        // (320,320)
    const float* __restrict__ w2,        // (320,190)
    const float* __restrict__ Wt,        // (32,16)
    const float* __restrict__ codebook)  // (500000,16)
{
    if (blockIdx.x < W12_TILES) {
        // ---- 32x32-tiled GEMM, 2x2 per thread ----
        __shared__ float As[32][33];
        __shared__ float Bs[32][33];
        const int tile = blockIdx.x;
        const int ti = tile / 6, tj = tile % 6;
        const int row0 = ti * 32, col0 = tj * 32;
        const int tid = threadIdx.x;
        const int tx = tid & 15, ty = tid >> 4;
        float a00 = 0.f, a01 = 0.f, a10 = 0.f, a11 = 0.f;
        for (int k0 = 0; k0 < FDq; k0 += 32) {
            #pragma unroll
            for (int i = tid; i < 32 * 32; i += 256) {
                int r = i >> 5, c = i & 31;
                As[r][c] = w1[(row0 + r) * FDq + k0 + c];
                int cb = col0 + c;
                Bs[r][c] = (cb < NIq) ? w2[(k0 + r) * NIq + cb] : 0.f;
            }
            __syncthreads();
            #pragma unroll
            for (int k = 0; k < 32; k++) {
                float x0 = As[ty * 2][k],  x1 = As[ty * 2 + 1][k];
                float y0 = Bs[k][tx * 2],  y1 = Bs[k][tx * 2 + 1];
                a00 += x0 * y0; a01 += x0 * y1;
                a10 += x1 * y0; a11 += x1 * y1;
            }
            __syncthreads();
        }
        int i0 = row0 + ty * 2, j0 = col0 + tx * 2;
        if (j0     < NIq) { g_W12T[ j0      * FDq + i0] = a00; g_W12T[ j0      * FDq + i0 + 1] = a10; }
        if (j0 + 1 < NIq) { g_W12T[(j0 + 1) * FDq + i0] = a01; g_W12T[(j0 + 1) * FDq + i0 + 1] = a11; }
    } else {
        // ---- codebook transform: one row per thread ----
        __shared__ __align__(16) float Ws[32 * 16];
        const int tid = threadIdx.x;
        Ws[tid]       = Wt[tid];
        Ws[tid + 256] = Wt[tid + 256];
        __syncthreads();
        int r = (blockIdx.x - W12_TILES) * 256 + tid;
        if (r >= NBq) return;
        const float4* cbv = (const float4*)(codebook + r * Dq);
        float c[16];
        #pragma unroll
        for (int q = 0; q < 4; q++) {
            float4 v = cbv[q];
            c[q * 4] = v.x; c[q * 4 + 1] = v.y; c[q * 4 + 2] = v.z; c[q * 4 + 3] = v.w;
        }
        const float4* Wv = (const float4*)Ws;   // [32][4]
        float4* o0 = (float4*)(g_CT0 + r * Dq);
        float4* o1 = (float4*)(g_CT1 + r * Dq);
        #pragma unroll
        for (int dq = 0; dq < 4; dq++) {
            float4 s0 = make_float4(0.f, 0.f, 0.f, 0.f);
            float4 s1 = make_float4(0.f, 0.f, 0.f, 0.f);
            #pragma unroll
            for (int k = 0; k < 16; k++) {
                float4 wt = Wv[k * 4 + dq];
                float4 wb = Wv[(16 + k) * 4 + dq];
                s0.x += c[k] * wt.x; s0.y += c[k] * wt.y; s0.z += c[k] * wt.z; s0.w += c[k] * wt.w;
                s1.x += c[k] * wb.x; s1.y += c[k] * wb.y; s1.z += c[k] * wb.z; s1.w += c[k] * wb.w;
            }
            o0[dq] = s0;
            o1[dq] = s1;
        }
    }
}

// ---------------------------------------------------------------------------
// K2: g_W = Z @ W12   via transposed W12T, float4 inner loop.
// One block = 32 batch rows; thread j owns column j.
// ---------------------------------------------------------------------------
#define TBq 32
__global__ __launch_bounds__(192) void k_senet(const float* __restrict__ z) {
    __shared__ __align__(16) float zs[TBq * FDq];   // 40 KB
    const int b0 = blockIdx.x * TBq;
    const int tid = threadIdx.x;
    {
        const float4* src = (const float4*)(z + b0 * FDq);
        float4* dst = (float4*)zs;
        for (int i = tid; i < TBq * FDq / 4; i += 192) dst[i] = src[i];
    }
    __syncthreads();
    const int j = tid;
    if (j >= NIq) return;
    float acc[TBq];
    #pragma unroll
    for (int b = 0; b < TBq; b++) acc[b] = 0.f;
    const float4* wp = (const float4*)(g_W12T + j * FDq);
    const float4* zv = (const float4*)zs;
    for (int k0 = 0; k0 < FDq / 4; k0++) {
        float4 w = wp[k0];
        #pragma unroll
        for (int b = 0; b < TBq; b++) {
            float4 v = zv[b * (FDq / 4) + k0];      // LDS broadcast
            acc[b] += v.x * w.x + v.y * w.y + v.z * w.z + v.w * w.w;
        }
    }
    #pragma unroll
    for (int b = 0; b < TBq; b++)
        g_W[(b0 + b) * NIq + j] = acc[b];
}

// ---------------------------------------------------------------------------
// K3: combine. One block per batch.
//  Phase 1: quad of threads per pair j: gather CT0[i0]+CT1[i1] (float4),
//           scale by w[b,j], store to smem (row stride 20 floats = 80 B,
//           a 16 B multiple, base 16 B aligned).
//  Phase 2: thread per (f,d): sum 19 pair contributions, write out.
// ---------------------------------------------------------------------------
__global__ __launch_bounds__(256) void k_combine(
    const int* __restrict__ hash_idx,    // (2, B, NI)
    const int* __restrict__ inter,       // (20, 19)
    float*     __restrict__ out)         // (B, 20, 16)
{
    __shared__ float ws[NIq];
    __shared__ __align__(16) float embw[NIq * 20];  // 15.2 KB
    __shared__ int   idxs[Fq * (Fq - 1)];

    const int b = blockIdx.x;
    const int tid = threadIdx.x;

    if (tid < NIq) ws[tid] = g_W[b * NIq + tid];
    for (int i = tid; i < Fq * (Fq - 1); i += 256) idxs[i] = inter[i];
    __syncthreads();

    const int* h0 = hash_idx + b * NIq;
    const int* h1 = hash_idx + Bq * NIq + b * NIq;
    const float4* ct0 = (const float4*)g_CT0;
    const float4* ct1 = (const float4*)g_CT1;

    for (int t = tid; t < NIq * 4; t += 256) {
        int j = t >> 2, q = t & 3;
        int i0 = h0[j], i1 = h1[j];
        float4 a = ct0[i0 * 4 + q];
        float4 c = ct1[i1 * 4 + q];
        float w = ws[j];
        float4 v;
        v.x = (a.x + c.x) * w; v.y = (a.y + c.y) * w;
        v.z = (a.z + c.z) * w; v.w = (a.w + c.w) * w;
        *((float4*)(embw + j * 20 + q * 4)) = v;
    }
    __syncthreads();

    for (int o = tid; o < Fq * Dq; o += 256) {
        int f = o >> 4, d = o & 15;
        const int* row = idxs + f * (Fq - 1);
        float s = 0.f;
        #pragma unroll
        for (int p = 0; p < Fq - 1; p++)
            s += embw[row[p] * 20 + d];
        out[b * Fq * Dq + o] = s;
    }
}

// ---------------------------------------------------------------------------
extern "C" void kernel_launch(void* const* d_in, const int* in_sizes, int n_in,
                              void* d_out, int out_size) {
    const float* origin   = (const float*)d_in[0];  // (B, F, D)
    const float* codebook = (const float*)d_in[1];  // (NB, D)
    const float* Wt       = (const float*)d_in[2];  // (32, 16)
    const float* w1       = (const float*)d_in[3];  // (320, 320)
    const float* w2       = (const float*)d_in[4];  // (320, 190)
    const int*   hash     = (const int*)d_in[5];    // (2, B, NI)
    const int*   inter    = (const int*)d_in[6];    // (20, 19)
    float*       out      = (float*)d_out;

    k_pre<<<W12_TILES + CT_BLOCKS, 256>>>(w1, w2, Wt, codebook);
    k_senet<<<Bq / TBq, 192>>>(origin);
    k_combine<<<Bq, 256>>>(hash, inter, out);
}